// round 10
// baseline (speedup 1.0000x reference)
#include <cuda_runtime.h>
#include <cuda_fp16.h>
#include <cstdint>

// Causal attention, warp-level fp16 mma.sync flash-attention, round 10:
// round-8 skeleton (3-stage cp.async, 32 q-rows/warp, heavy-first)
// + quarter-split softmax (128 regs, proven in r9)
// + Q smem staging overlaid on K buffers -> smem 55.5KB -> 4 CTAs/SM (16 warps).
// B=4, H=8, S=2048, D=64.

#define S_LEN 2048
#define BM 128
#define BN 64
#define HD 64
#define NT 128
#define QSC 0.18033688011112042f   /* 0.125 * log2(e) */
#define KST 72                     /* padded halves per SMEM row (144 B) */
#define TOT (4*8*2048*64)
#define KVB 9216                   /* one K or V tile buffer: 64*72*2 bytes */

__device__ __align__(16) __half KHg[TOT];
__device__ __align__(16) __half VHg[TOT];

// ---- prepass: fp32 -> fp16 for K and V (once) ----
__global__ __launch_bounds__(256)
void conv_kv(const float* __restrict__ K, const float* __restrict__ V) {
    int i = (blockIdx.x * 256 + threadIdx.x) * 8;
    float4 a = *reinterpret_cast<const float4*>(K + i);
    float4 b = *reinterpret_cast<const float4*>(K + i + 4);
    __half2 h[4] = { __floats2half2_rn(a.x, a.y), __floats2half2_rn(a.z, a.w),
                     __floats2half2_rn(b.x, b.y), __floats2half2_rn(b.z, b.w) };
    *reinterpret_cast<float4*>(&KHg[i]) = *reinterpret_cast<const float4*>(h);
    a = *reinterpret_cast<const float4*>(V + i);
    b = *reinterpret_cast<const float4*>(V + i + 4);
    __half2 g[4] = { __floats2half2_rn(a.x, a.y), __floats2half2_rn(a.z, a.w),
                     __floats2half2_rn(b.x, b.y), __floats2half2_rn(b.z, b.w) };
    *reinterpret_cast<float4*>(&VHg[i]) = *reinterpret_cast<const float4*>(g);
}

__device__ __forceinline__ void ldsm_x4(uint32_t* r, uint32_t a) {
    asm volatile("ldmatrix.sync.aligned.m8n8.x4.shared.b16 {%0,%1,%2,%3}, [%4];"
                 : "=r"(r[0]), "=r"(r[1]), "=r"(r[2]), "=r"(r[3]) : "r"(a));
}
__device__ __forceinline__ void ldsm_x4t(uint32_t* r, uint32_t a) {
    asm volatile("ldmatrix.sync.aligned.m8n8.x4.trans.shared.b16 {%0,%1,%2,%3}, [%4];"
                 : "=r"(r[0]), "=r"(r[1]), "=r"(r[2]), "=r"(r[3]) : "r"(a));
}
__device__ __forceinline__ void mma16816(float* c, const uint32_t* a, uint32_t b0, uint32_t b1) {
    asm volatile("mma.sync.aligned.m16n8k16.row.col.f32.f16.f16.f32 "
        "{%0,%1,%2,%3}, {%4,%5,%6,%7}, {%8,%9}, {%0,%1,%2,%3};"
        : "+f"(c[0]), "+f"(c[1]), "+f"(c[2]), "+f"(c[3])
        : "r"(a[0]), "r"(a[1]), "r"(a[2]), "r"(a[3]), "r"(b0), "r"(b1));
}
// pack {lo=s0, hi=s1} to f16x2, then 2^x per half
__device__ __forceinline__ uint32_t exph2(float s1, float s0) {
    uint32_t d;
    asm("{\n\t.reg .b32 t;\n\t"
        "cvt.rn.f16x2.f32 t, %1, %2;\n\t"
        "ex2.approx.f16x2 %0, t;\n\t}"
        : "=r"(d) : "f"(s1), "f"(s0));
    return d;
}
__device__ __forceinline__ void cp16(uint32_t dst, const void* src) {
    asm volatile("cp.async.cg.shared.global [%0], [%1], 16;" :: "r"(dst), "l"(src) : "memory");
}
#define CP_COMMIT() asm volatile("cp.async.commit_group;" ::: "memory")
#define CP_WAIT(n)  asm volatile("cp.async.wait_group %0;" :: "n"(n) : "memory")

// dynamic smem layout (bytes): Q staging OVERLAYS the K buffer region
// (Q is consumed into registers before any cp.async is issued)
#define SM_K   0                    /* 3 * KVB = 27648; Q staged at 0..18431 first */
#define SM_V   27648                /* 3 * KVB = 27648 */
#define SM_TOTAL 55552              /* +256 pad: ones-block ldsm tail overread */

__global__ __launch_bounds__(NT, 4)
void fa_hmma8(const float* __restrict__ Q, float* __restrict__ O)
{
    extern __shared__ char smem[];
    __half* Qs = reinterpret_cast<__half*>(smem);   // transient staging over SM_K

    const int tid = threadIdx.x;
    const int w = tid >> 5, lane = tid & 31;
    const int g = lane >> 3, r8 = lane & 7;
    const int qt = (int)gridDim.x - 1 - (int)blockIdx.x;   // heavy q-tiles first
    const int bh = blockIdx.y;
    const int q0 = qt * BM;
    const int ktmax = 2 * qt + 1;

    const size_t base = (size_t)bh * S_LEN * HD;
    const float* Qb = Q + base;
    const __half* KH = KHg + base;
    const __half* VH = VHg + base;
    float* Ob = O + base;

    const uint32_t sb32 = (uint32_t)__cvta_generic_to_shared(smem);
    const uint32_t kb32 = sb32 + SM_K;
    const uint32_t vb32 = sb32 + SM_V;

    // ---- stage Q tile in smem (over K region), pre-scaled fp32 -> fp16 ----
    #pragma unroll
    for (int it = 0; it < 16; it++) {
        int i = tid + it * NT;
        int r = i >> 4, c = (i & 15) << 2;
        float4 v = *reinterpret_cast<const float4*>(Qb + (size_t)(q0 + r) * HD + c);
        half2* dst = reinterpret_cast<half2*>(&Qs[r * KST + c]);
        dst[0] = __floats2half2_rn(v.x * QSC, v.y * QSC);
        dst[1] = __floats2half2_rn(v.z * QSC, v.w * QSC);
    }
    __syncthreads();

    // ---- Q A-fragments in registers: 2 row-blocks of 16 ----
    uint32_t qa[2][4][4];
    #pragma unroll
    for (int rb = 0; rb < 2; rb++) {
        int row = w * 32 + rb * 16 + (g & 1) * 8 + r8;
        #pragma unroll
        for (int kb = 0; kb < 4; kb++) {
            int colh = kb * 16 + (g >> 1) * 8;
            ldsm_x4(qa[rb][kb], sb32 + (uint32_t)(row * KST + colh) * 2);
        }
    }
    __syncthreads();   // all warps done reading Q; K region reusable

    // ---- init ones-column (col 64 = 1.0, 65..71 = 0) in all 3 V buffers ----
    for (int idx = tid; idx < 192; idx += NT) {
        int b = idx >> 6, r = idx & 63;
        *reinterpret_cast<uint4*>(smem + SM_V + b * KVB + r * (KST * 2) + 128) =
            make_uint4(0x00003C00u, 0u, 0u, 0u);
    }

    // cp.async: 512 16B-chunks per tile per tensor, 4 per thread
    uint32_t kd[4]; int cro[4], cco[4];
    #pragma unroll
    for (int i = 0; i < 4; i++) {
        int c = tid + i * NT;
        cro[i] = c >> 3; cco[i] = (c & 7) << 3;
        kd[i] = (uint32_t)(cro[i] * KST + cco[i]) * 2;
    }

    // ---- prologue: issue tiles 0 and 1 ----
    #pragma unroll
    for (int i = 0; i < 4; i++) {
        cp16(kb32 + kd[i], KH + cro[i] * HD + cco[i]);
        cp16(vb32 + kd[i], VH + cro[i] * HD + cco[i]);
    }
    CP_COMMIT();
    {
        const __half* ks = KH + (size_t)BN * HD;
        const __half* vs = VH + (size_t)BN * HD;
        #pragma unroll
        for (int i = 0; i < 4; i++) {
            cp16(kb32 + KVB + kd[i], ks + cro[i] * HD + cco[i]);
            cp16(vb32 + KVB + kd[i], vs + cro[i] * HD + cco[i]);
        }
        CP_COMMIT();
    }

    float o[2][8][4];
    #pragma unroll
    for (int rb = 0; rb < 2; rb++)
        #pragma unroll
        for (int a = 0; a < 8; a++)
            #pragma unroll
            for (int b = 0; b < 4; b++) o[rb][a][b] = 0.f;
    float ol[2][4];
    #pragma unroll
    for (int rb = 0; rb < 2; rb++)
        #pragma unroll
        for (int b = 0; b < 4; b++) ol[rb][b] = 0.f;

    const int qgA = q0 + w * 32 + (lane >> 2);
    const uint32_t koff = (uint32_t)(((g & 1) * 8 + r8) * KST + (g >> 1) * 8) * 2;

    for (int kt = 0; kt <= ktmax; kt++) {
        const int k0 = kt * BN;
        CP_WAIT(1);            // tile kt resident
        __syncthreads();       // buffer (kt+2)%3 free

        // ---- issue tile kt+2 ----
        {
            int kn = min(kt + 2, ktmax) * BN;
            uint32_t bo = (uint32_t)((kt + 2) % 3) * KVB;
            const __half* ks = KH + (size_t)kn * HD;
            const __half* vs = VH + (size_t)kn * HD;
            #pragma unroll
            for (int i = 0; i < 4; i++) {
                cp16(kb32 + bo + kd[i], ks + cro[i] * HD + cco[i]);
                cp16(vb32 + bo + kd[i], vs + cro[i] * HD + cco[i]);
            }
            CP_COMMIT();
        }

        const uint32_t kbase = kb32 + (uint32_t)(kt % 3) * KVB;
        const uint32_t vbase = vb32 + (uint32_t)(kt % 3) * KVB;
        const bool dg = (kt >= 2 * qt);

        // ---- four 16-column chunks: QK -> exp -> PV (128-reg live set) ----
        #pragma unroll
        for (int ch = 0; ch < 4; ch++) {
            float sacc[2][2][4];
            #pragma unroll
            for (int rb = 0; rb < 2; rb++)
                #pragma unroll
                for (int a = 0; a < 2; a++)
                    #pragma unroll
                    for (int b = 0; b < 4; b++) sacc[rb][a][b] = 0.f;

            #pragma unroll
            for (int kb = 0; kb < 4; kb++) {
                uint32_t bk[4];
                ldsm_x4(bk, kbase + koff + (uint32_t)(ch * 16 * KST + kb * 16) * 2);
                #pragma unroll
                for (int rb = 0; rb < 2; rb++) {
                    mma16816(sacc[rb][0], qa[rb][kb], bk[0], bk[2]);
                    mma16816(sacc[rb][1], qa[rb][kb], bk[1], bk[3]);
                }
            }

            uint32_t ph[2][2][2];
            #pragma unroll
            for (int rb = 0; rb < 2; rb++) {
                #pragma unroll
                for (int nb = 0; nb < 2; nb++) {
                    float s0 = sacc[rb][nb][0], s1 = sacc[rb][nb][1];
                    float s2 = sacc[rb][nb][2], s3 = sacc[rb][nb][3];
                    if (dg) {
                        int c0 = k0 + ch * 16 + nb * 8 + ((lane & 3) << 1);
                        int r0 = qgA + rb * 16;
                        if (c0     > r0)     s0 = -30000.f;
                        if (c0 + 1 > r0)     s1 = -30000.f;
                        if (c0     > r0 + 8) s2 = -30000.f;
                        if (c0 + 1 > r0 + 8) s3 = -30000.f;
                    }
                    ph[rb][nb][0] = exph2(s1, s0);
                    ph[rb][nb][1] = exph2(s3, s2);
                }
            }

            #pragma unroll
            for (int nbp = 0; nbp < 4; nbp++) {
                uint32_t bv[4];
                ldsm_x4t(bv, vbase + koff + (uint32_t)(ch * 16 * KST + nbp * 16) * 2);
                #pragma unroll
                for (int rb = 0; rb < 2; rb++) {
                    uint32_t pa[4] = { ph[rb][0][0], ph[rb][0][1],
                                       ph[rb][1][0], ph[rb][1][1] };
                    mma16816(o[rb][2 * nbp],     pa, bv[0], bv[1]);
                    mma16816(o[rb][2 * nbp + 1], pa, bv[2], bv[3]);
                }
            }
            uint32_t bo1[4];
            ldsm_x4t(bo1, vbase + koff + (uint32_t)(ch * 16 * KST + 64) * 2);
            #pragma unroll
            for (int rb = 0; rb < 2; rb++) {
                uint32_t pa[4] = { ph[rb][0][0], ph[rb][0][1],
                                   ph[rb][1][0], ph[rb][1][1] };
                mma16816(ol[rb], pa, bo1[0], bo1[1]);
            }
        }
    }
    CP_WAIT(0);

    // ---- normalize and store ----
    #pragma unroll
    for (int rb = 0; rb < 2; rb++) {
        const float l0 = __shfl_sync(0xffffffffu, ol[rb][0], lane & 28);
        const float l1 = __shfl_sync(0xffffffffu, ol[rb][2], lane & 28);
        const float inv0 = 1.f / l0;
        const float inv1 = 1.f / l1;
        const int row0 = q0 + w * 32 + rb * 16 + (lane >> 2);
        const int colb = (lane & 3) << 1;
        #pragma unroll
        for (int nb = 0; nb < 8; nb++) {
            int col = nb * 8 + colb;
            *reinterpret_cast<float2*>(Ob + (size_t)row0 * HD + col) =
                make_float2(o[rb][nb][0] * inv0, o[rb][nb][1] * inv0);
            *reinterpret_cast<float2*>(Ob + (size_t)(row0 + 8) * HD + col) =
                make_float2(o[rb][nb][2] * inv1, o[rb][nb][3] * inv1);
        }
    }
}

extern "C" void kernel_launch(void* const* d_in, const int* in_sizes, int n_in,
                              void* d_out, int out_size) {
    const float* Q = (const float*)d_in[0];
    const float* K = (const float*)d_in[1];
    const float* V = (const float*)d_in[2];
    float* O = (float*)d_out;
    (void)in_sizes; (void)n_in; (void)out_size;

    conv_kv<<<TOT / (256 * 8), 256>>>(K, V);

    cudaFuncSetAttribute(fa_hmma8, cudaFuncAttributeMaxDynamicSharedMemorySize, SM_TOTAL);
    dim3 grid(S_LEN / BM, 4 * 8);
    fa_hmma8<<<grid, NT, SM_TOTAL>>>(Q, O);
}

// round 11
// speedup vs baseline: 1.8364x; 1.8364x over previous
#include <cuda_runtime.h>
#include <cuda_fp16.h>
#include <cstdint>

// Causal attention, warp-level fp16 mma.sync flash-attention, round 11:
// r8 inner kernel (best: 82.7us) + grid-level load balancing:
// tasks with qt>=8 split into two key-range halves (max cost 32->16 tiles),
// heavy-first static task table, fp32 partial outputs + combine kernel.
// B=4, H=8, S=2048, D=64.

#define S_LEN 2048
#define BM 128
#define BN 64
#define HD 64
#define NT 128
#define QSC 0.18033688011112042f   /* 0.125 * log2(e) */
#define KST 72                     /* padded halves per SMEM row (144 B) */
#define TOT (4*8*2048*64)
#define KVB 9216                   /* one K or V tile buffer: 64*72*2 bytes */

__device__ __align__(16) __half KHg[TOT];
__device__ __align__(16) __half VHg[TOT];
__device__ __align__(16) float OPg[32 * 8 * 2 * (BM * HD)];  // split partials, 16MB
__device__ __align__(16) float LPg[32 * 8 * 2 * BM];         // split row-sums

// task table: {qt, kt0, kt1, part(-1 = unsplit)} sorted by cost desc
__device__ const int4 TASKS[24] = {
    { 7,  0, 15, -1}, {15,  0, 15,  0}, {15, 16, 31,  1},
    {14,  0, 14,  0}, {14, 15, 29,  1},
    { 6,  0, 13, -1}, {13,  0, 13,  0}, {13, 14, 27,  1},
    {12,  0, 12,  0}, {12, 13, 25,  1},
    { 5,  0, 11, -1}, {11,  0, 11,  0}, {11, 12, 23,  1},
    {10,  0, 10,  0}, {10, 11, 21,  1},
    { 4,  0,  9, -1}, { 9,  0,  9,  0}, { 9, 10, 19,  1},
    { 8,  0,  8,  0}, { 8,  9, 17,  1},
    { 3,  0,  7, -1}, { 2,  0,  5, -1}, { 1,  0,  3, -1}, { 0,  0,  1, -1}
};

// ---- prepass: fp32 -> fp16 for K and V (once) ----
__global__ __launch_bounds__(256)
void conv_kv(const float* __restrict__ K, const float* __restrict__ V) {
    int i = (blockIdx.x * 256 + threadIdx.x) * 8;
    float4 a = *reinterpret_cast<const float4*>(K + i);
    float4 b = *reinterpret_cast<const float4*>(K + i + 4);
    __half2 h[4] = { __floats2half2_rn(a.x, a.y), __floats2half2_rn(a.z, a.w),
                     __floats2half2_rn(b.x, b.y), __floats2half2_rn(b.z, b.w) };
    *reinterpret_cast<float4*>(&KHg[i]) = *reinterpret_cast<const float4*>(h);
    a = *reinterpret_cast<const float4*>(V + i);
    b = *reinterpret_cast<const float4*>(V + i + 4);
    __half2 g[4] = { __floats2half2_rn(a.x, a.y), __floats2half2_rn(a.z, a.w),
                     __floats2half2_rn(b.x, b.y), __floats2half2_rn(b.z, b.w) };
    *reinterpret_cast<float4*>(&VHg[i]) = *reinterpret_cast<const float4*>(g);
}

__device__ __forceinline__ void ldsm_x4(uint32_t* r, uint32_t a) {
    asm volatile("ldmatrix.sync.aligned.m8n8.x4.shared.b16 {%0,%1,%2,%3}, [%4];"
                 : "=r"(r[0]), "=r"(r[1]), "=r"(r[2]), "=r"(r[3]) : "r"(a));
}
__device__ __forceinline__ void ldsm_x4t(uint32_t* r, uint32_t a) {
    asm volatile("ldmatrix.sync.aligned.m8n8.x4.trans.shared.b16 {%0,%1,%2,%3}, [%4];"
                 : "=r"(r[0]), "=r"(r[1]), "=r"(r[2]), "=r"(r[3]) : "r"(a));
}
__device__ __forceinline__ void mma16816(float* c, const uint32_t* a, uint32_t b0, uint32_t b1) {
    asm volatile("mma.sync.aligned.m16n8k16.row.col.f32.f16.f16.f32 "
        "{%0,%1,%2,%3}, {%4,%5,%6,%7}, {%8,%9}, {%0,%1,%2,%3};"
        : "+f"(c[0]), "+f"(c[1]), "+f"(c[2]), "+f"(c[3])
        : "r"(a[0]), "r"(a[1]), "r"(a[2]), "r"(a[3]), "r"(b0), "r"(b1));
}
__device__ __forceinline__ uint32_t exph2(float s1, float s0) {
    uint32_t d;
    asm("{\n\t.reg .b32 t;\n\t"
        "cvt.rn.f16x2.f32 t, %1, %2;\n\t"
        "ex2.approx.f16x2 %0, t;\n\t}"
        : "=r"(d) : "f"(s1), "f"(s0));
    return d;
}
__device__ __forceinline__ void cp16(uint32_t dst, const void* src) {
    asm volatile("cp.async.cg.shared.global [%0], [%1], 16;" :: "r"(dst), "l"(src) : "memory");
}
#define CP_COMMIT() asm volatile("cp.async.commit_group;" ::: "memory")
#define CP_WAIT(n)  asm volatile("cp.async.wait_group %0;" :: "n"(n) : "memory")

// dynamic smem layout (bytes)
#define SM_Q   0                    /* 128*72*2 = 18432 */
#define SM_K   18432                /* 3 * KVB = 27648 */
#define SM_V   46080                /* 3 * KVB = 27648 */
#define SM_TOTAL 73984              /* +256 pad: ones-block ldsm tail overread */

__global__ __launch_bounds__(NT, 3)
void fa_hmma9(const float* __restrict__ Q, float* __restrict__ O)
{
    extern __shared__ char smem[];
    __half* Qs = reinterpret_cast<__half*>(smem + SM_Q);

    const int tid = threadIdx.x;
    const int w = tid >> 5, lane = tid & 31;
    const int g = lane >> 3, r8 = lane & 7;
    const int bh = blockIdx.x;
    const int4 tk = TASKS[blockIdx.y];
    const int qt = tk.x, kt0 = tk.y, kt1 = tk.z, part = tk.w;
    const int q0 = qt * BM;

    const size_t base = (size_t)bh * S_LEN * HD;
    const float* Qb = Q + base;
    const __half* KH = KHg + base;
    const __half* VH = VHg + base;
    float* Ob = O + base;

    const uint32_t sb32 = (uint32_t)__cvta_generic_to_shared(smem);
    const uint32_t kb32 = sb32 + SM_K;
    const uint32_t vb32 = sb32 + SM_V;

    // ---- init ones-column (col 64 = 1.0, 65..71 = 0) in all 3 V buffers ----
    for (int idx = tid; idx < 192; idx += NT) {
        int b = idx >> 6, r = idx & 63;
        *reinterpret_cast<uint4*>(smem + SM_V + b * KVB + r * (KST * 2) + 128) =
            make_uint4(0x00003C00u, 0u, 0u, 0u);
    }

    // cp.async: 512 16B-chunks per tile per tensor, 4 per thread
    uint32_t kd[4]; int cro[4], cco[4];
    #pragma unroll
    for (int i = 0; i < 4; i++) {
        int c = tid + i * NT;
        cro[i] = c >> 3; cco[i] = (c & 7) << 3;
        kd[i] = (uint32_t)(cro[i] * KST + cco[i]) * 2;
    }

    // ---- prologue: issue tiles kt0 and kt0+1 (every task has >= 2 tiles) ----
    {
        const __half* ks = KH + (size_t)kt0 * BN * HD;
        const __half* vs = VH + (size_t)kt0 * BN * HD;
        #pragma unroll
        for (int i = 0; i < 4; i++) {
            cp16(kb32 + (uint32_t)(kt0 % 3) * KVB + kd[i], ks + cro[i] * HD + cco[i]);
            cp16(vb32 + (uint32_t)(kt0 % 3) * KVB + kd[i], vs + cro[i] * HD + cco[i]);
        }
        CP_COMMIT();
        ks += (size_t)BN * HD; vs += (size_t)BN * HD;
        #pragma unroll
        for (int i = 0; i < 4; i++) {
            cp16(kb32 + (uint32_t)((kt0 + 1) % 3) * KVB + kd[i], ks + cro[i] * HD + cco[i]);
            cp16(vb32 + (uint32_t)((kt0 + 1) % 3) * KVB + kd[i], vs + cro[i] * HD + cco[i]);
        }
        CP_COMMIT();
    }

    // ---- load Q tile, pre-scaled, fp32 -> fp16 ----
    #pragma unroll
    for (int it = 0; it < 16; it++) {
        int i = tid + it * NT;
        int r = i >> 4, c = (i & 15) << 2;
        float4 v = *reinterpret_cast<const float4*>(Qb + (size_t)(q0 + r) * HD + c);
        half2* dst = reinterpret_cast<half2*>(&Qs[r * KST + c]);
        dst[0] = __floats2half2_rn(v.x * QSC, v.y * QSC);
        dst[1] = __floats2half2_rn(v.z * QSC, v.w * QSC);
    }
    __syncthreads();

    // ---- Q A-fragments in registers: 2 row-blocks of 16 ----
    uint32_t qa[2][4][4];
    #pragma unroll
    for (int rb = 0; rb < 2; rb++) {
        int row = w * 32 + rb * 16 + (g & 1) * 8 + r8;
        #pragma unroll
        for (int kb = 0; kb < 4; kb++) {
            int colh = kb * 16 + (g >> 1) * 8;
            ldsm_x4(qa[rb][kb], sb32 + (uint32_t)(row * KST + colh) * 2);
        }
    }

    float o[2][8][4];
    #pragma unroll
    for (int rb = 0; rb < 2; rb++)
        #pragma unroll
        for (int a = 0; a < 8; a++)
            #pragma unroll
            for (int b = 0; b < 4; b++) o[rb][a][b] = 0.f;
    float ol[2][4];
    #pragma unroll
    for (int rb = 0; rb < 2; rb++)
        #pragma unroll
        for (int b = 0; b < 4; b++) ol[rb][b] = 0.f;

    const int qgA = q0 + w * 32 + (lane >> 2);
    const uint32_t koff = (uint32_t)(((g & 1) * 8 + r8) * KST + (g >> 1) * 8) * 2;

    for (int kt = kt0; kt <= kt1; kt++) {
        const int k0 = kt * BN;
        CP_WAIT(1);            // tile kt resident
        __syncthreads();       // buffer (kt+2)%3 free

        // ---- issue tile kt+2 ----
        {
            int kn = min(kt + 2, kt1) * BN;
            uint32_t bo = (uint32_t)((kt + 2) % 3) * KVB;
            const __half* ks = KH + (size_t)kn * HD;
            const __half* vs = VH + (size_t)kn * HD;
            #pragma unroll
            for (int i = 0; i < 4; i++) {
                cp16(kb32 + bo + kd[i], ks + cro[i] * HD + cco[i]);
                cp16(vb32 + bo + kd[i], vs + cro[i] * HD + cco[i]);
            }
            CP_COMMIT();
        }

        const uint32_t kbase = kb32 + (uint32_t)(kt % 3) * KVB;
        const uint32_t vbase = vb32 + (uint32_t)(kt % 3) * KVB;
        const bool dg = (kt >= 2 * qt);

        // ---- two 32-column halves: QK -> exp -> PV (r8 structure) ----
        #pragma unroll
        for (int hf = 0; hf < 2; hf++) {
            float sacc[2][4][4];
            #pragma unroll
            for (int rb = 0; rb < 2; rb++)
                #pragma unroll
                for (int a = 0; a < 4; a++)
                    #pragma unroll
                    for (int b = 0; b < 4; b++) sacc[rb][a][b] = 0.f;

            #pragma unroll
            for (int kb = 0; kb < 4; kb++) {
                #pragma unroll
                for (int nbp = 0; nbp < 2; nbp++) {
                    uint32_t bk[4];
                    ldsm_x4(bk, kbase + koff +
                            (uint32_t)(((hf * 2 + nbp) * 16) * KST + kb * 16) * 2);
                    #pragma unroll
                    for (int rb = 0; rb < 2; rb++) {
                        mma16816(sacc[rb][2 * nbp],     qa[rb][kb], bk[0], bk[2]);
                        mma16816(sacc[rb][2 * nbp + 1], qa[rb][kb], bk[1], bk[3]);
                    }
                }
            }

            uint32_t ph[2][4][2];
            #pragma unroll
            for (int rb = 0; rb < 2; rb++) {
                #pragma unroll
                for (int nb = 0; nb < 4; nb++) {
                    float s0 = sacc[rb][nb][0], s1 = sacc[rb][nb][1];
                    float s2 = sacc[rb][nb][2], s3 = sacc[rb][nb][3];
                    if (dg) {
                        int c0 = k0 + hf * 32 + nb * 8 + ((lane & 3) << 1);
                        int r0 = qgA + rb * 16;
                        if (c0     > r0)     s0 = -30000.f;
                        if (c0 + 1 > r0)     s1 = -30000.f;
                        if (c0     > r0 + 8) s2 = -30000.f;
                        if (c0 + 1 > r0 + 8) s3 = -30000.f;
                    }
                    ph[rb][nb][0] = exph2(s1, s0);
                    ph[rb][nb][1] = exph2(s3, s2);
                }
            }

            #pragma unroll
            for (int kbl = 0; kbl < 2; kbl++) {
                int kbk = hf * 2 + kbl;
                #pragma unroll
                for (int nbp = 0; nbp < 4; nbp++) {
                    uint32_t bv[4];
                    ldsm_x4t(bv, vbase + koff +
                             (uint32_t)(kbk * 16 * KST + nbp * 16) * 2);
                    #pragma unroll
                    for (int rb = 0; rb < 2; rb++) {
                        uint32_t pa[4] = { ph[rb][2 * kbl][0], ph[rb][2 * kbl][1],
                                           ph[rb][2 * kbl + 1][0], ph[rb][2 * kbl + 1][1] };
                        mma16816(o[rb][2 * nbp],     pa, bv[0], bv[1]);
                        mma16816(o[rb][2 * nbp + 1], pa, bv[2], bv[3]);
                    }
                }
                uint32_t bo1[4];
                ldsm_x4t(bo1, vbase + koff + (uint32_t)(kbk * 16 * KST + 64) * 2);
                #pragma unroll
                for (int rb = 0; rb < 2; rb++) {
                    uint32_t pa[4] = { ph[rb][2 * kbl][0], ph[rb][2 * kbl][1],
                                       ph[rb][2 * kbl + 1][0], ph[rb][2 * kbl + 1][1] };
                    mma16816(ol[rb], pa, bo1[0], bo1[1]);
                }
            }
        }
    }
    CP_WAIT(0);

    if (part < 0) {
        // ---- unsplit: normalize and store directly ----
        #pragma unroll
        for (int rb = 0; rb < 2; rb++) {
            const float l0 = __shfl_sync(0xffffffffu, ol[rb][0], lane & 28);
            const float l1 = __shfl_sync(0xffffffffu, ol[rb][2], lane & 28);
            const float inv0 = 1.f / l0;
            const float inv1 = 1.f / l1;
            const int row0 = q0 + w * 32 + rb * 16 + (lane >> 2);
            const int colb = (lane & 3) << 1;
            #pragma unroll
            for (int nb = 0; nb < 8; nb++) {
                int col = nb * 8 + colb;
                *reinterpret_cast<float2*>(Ob + (size_t)row0 * HD + col) =
                    make_float2(o[rb][nb][0] * inv0, o[rb][nb][1] * inv0);
                *reinterpret_cast<float2*>(Ob + (size_t)(row0 + 8) * HD + col) =
                    make_float2(o[rb][nb][2] * inv1, o[rb][nb][3] * inv1);
            }
        }
    } else {
        // ---- split: write unnormalized partials + row sums ----
        const int sid = (bh * 8 + (qt - 8)) * 2 + part;
        float* op = OPg + (size_t)sid * (BM * HD);
        float* lp = LPg + (size_t)sid * BM;
        #pragma unroll
        for (int rb = 0; rb < 2; rb++) {
            const int row0 = w * 32 + rb * 16 + (lane >> 2);
            const int colb = (lane & 3) << 1;
            #pragma unroll
            for (int nb = 0; nb < 8; nb++) {
                int col = nb * 8 + colb;
                *reinterpret_cast<float2*>(op + row0 * HD + col) =
                    make_float2(o[rb][nb][0], o[rb][nb][1]);
                *reinterpret_cast<float2*>(op + (row0 + 8) * HD + col) =
                    make_float2(o[rb][nb][2], o[rb][nb][3]);
            }
            if ((lane & 3) == 0) {
                lp[row0]     = ol[rb][0];
                lp[row0 + 8] = ol[rb][2];
            }
        }
    }
}

// ---- combine: O = (P0 + P1) / (l0 + l1) for split q-tiles (qt 8..15) ----
__global__ __launch_bounds__(128)
void fa_combine(float* __restrict__ O) {
    int t = blockIdx.x * 128 + threadIdx.x;   // 262144 threads x 8 floats
    int e = t * 8;
    int rq  = e >> 13;                         // (bh*8 + qt-8)
    int rem = e & 8191;
    int row = rem >> 6;
    float l0 = LPg[(rq * 2 + 0) * BM + row];
    float l1 = LPg[(rq * 2 + 1) * BM + row];
    float inv = 1.f / (l0 + l1);
    const float4* p0 = reinterpret_cast<const float4*>(OPg + (size_t)(rq * 2 + 0) * (BM * HD) + rem);
    const float4* p1 = reinterpret_cast<const float4*>(OPg + (size_t)(rq * 2 + 1) * (BM * HD) + rem);
    int bh = rq >> 3, qt = (rq & 7) + 8;
    float* out = O + (size_t)bh * S_LEN * HD + (size_t)qt * BM * HD + rem;
    float4 a = p0[0], b = p1[0];
    reinterpret_cast<float4*>(out)[0] =
        make_float4((a.x + b.x) * inv, (a.y + b.y) * inv, (a.z + b.z) * inv, (a.w + b.w) * inv);
    a = p0[1]; b = p1[1];
    reinterpret_cast<float4*>(out)[1] =
        make_float4((a.x + b.x) * inv, (a.y + b.y) * inv, (a.z + b.z) * inv, (a.w + b.w) * inv);
}

extern "C" void kernel_launch(void* const* d_in, const int* in_sizes, int n_in,
                              void* d_out, int out_size) {
    const float* Q = (const float*)d_in[0];
    const float* K = (const float*)d_in[1];
    const float* V = (const float*)d_in[2];
    float* O = (float*)d_out;
    (void)in_sizes; (void)n_in; (void)out_size;

    conv_kv<<<TOT / (256 * 8), 256>>>(K, V);

    cudaFuncSetAttribute(fa_hmma9, cudaFuncAttributeMaxDynamicSharedMemorySize, SM_TOTAL);
    dim3 grid(32, 24);                 // x = bh (fast), y = task (heavy-first)
    fa_hmma9<<<grid, NT, SM_TOTAL>>>(Q, O);

    fa_combine<<<2048, 128>>>(O);      // 32*8 split tiles * 128*64 / (128*8)
}